// round 9
// baseline (speedup 1.0000x reference)
#include <cuda_runtime.h>
#include <cuda_fp16.h>
#include <math.h>

#define DD 128
#define HH 128
#define WW 128
#define HW (HH*WW)
#define NVOX (DD*HH*WW)
#define RAD 15
#define TAPS 31

// fp16 intermediates: pass1 out (8 labels x 3 h-orders), pass2 out (8 x 6 combos)
__device__ __half g_s1h[(size_t)24 * NVOX];   // ~100 MB
__device__ __half g_s2h[(size_t)48 * NVOX];   // ~201 MB
__device__ float  g_w0[TAPS];

// ---------------- f32x2 packed helpers ----------------
typedef unsigned long long u64;

__device__ __forceinline__ u64 pk2(float lo, float hi) {
    u64 r; asm("mov.b64 %0, {%1, %2};" : "=l"(r) : "f"(lo), "f"(hi)); return r;
}
__device__ __forceinline__ void upk2(float& lo, float& hi, u64 v) {
    asm("mov.b64 {%0, %1}, %2;" : "=f"(lo), "=f"(hi) : "l"(v));
}
__device__ __forceinline__ u64 ffma2(u64 a, u64 b, u64 c) {
    u64 r; asm("fma.rn.f32x2 %0, %1, %2, %3;" : "=l"(r) : "l"(a), "l"(b), "l"(c)); return r;
}

// ---------------------------------------------------------------------------
// Weight init: float expf + warp reduction.
// ---------------------------------------------------------------------------
__global__ void init_weights_kernel() {
    int t = threadIdx.x;   // 32 threads
    float d = (float)(t - RAD);
    float v = (t < TAPS) ? expf(-0.5f * d * d / 25.0f) : 0.0f;
    float s = v;
#pragma unroll
    for (int o = 16; o; o >>= 1) s += __shfl_xor_sync(0xffffffffu, s, o);
    if (t < TAPS) g_w0[t] = v / s;
}

// ---------------------------------------------------------------------------
// Pass 1: blur along H. One-hot: per tap add (k0,k1) to the matched label's
// float2 slot + k2 to a scalar slot. Slot 8 is a dummy sink for label 0.
// ---------------------------------------------------------------------------
__global__ __launch_bounds__(128) void pass1_kernel(const int* __restrict__ seg) {
    __shared__ float2 accA[9 * 128];   // (k0,k1) per label slot
    __shared__ float  accB[9 * 128];   // k2 per label slot
    __shared__ float  sw0[TAPS];
    int w = threadIdx.x;
    int h = blockIdx.x;
    int d = blockIdx.y;
    if (w < TAPS) sw0[w] = g_w0[w];
#pragma unroll
    for (int i = 0; i < 9; ++i) {
        accA[i * 128 + w] = make_float2(0.0f, 0.0f);
        accB[i * 128 + w] = 0.0f;
    }
    __syncthreads();   // for sw0 only

    int lo = h - RAD; if (lo < 0) lo = 0;
    int hi = h + RAD; if (hi > HH - 1) hi = HH - 1;
    const int* p = seg + (size_t)d * HW + w;
    for (int hh = lo; hh <= hi; ++hh) {
        int s = __ldg(p + (size_t)hh * WW);
        int t = hh - h + RAD;
        float k0 = sw0[t];
        float dd = (float)(hh - h);
        float k1 = k0 * dd;
        float k2 = k1 * dd;
        int slot = (s == 0) ? 8 : (s - 1);
        int off  = slot * 128 + w;
        float2 a = accA[off];
        a.x += k0; a.y += k1;
        accA[off] = a;
        accB[off] += k2;
    }
    size_t idx = (size_t)d * HW + (size_t)h * WW + w;
#pragma unroll
    for (int l = 0; l < 8; ++l) {
        float2 a = accA[l * 128 + w];
        float  b = accB[l * 128 + w];
        g_s1h[(size_t)(l * 3 + 0) * NVOX + idx] = __float2half(a.x);
        g_s1h[(size_t)(l * 3 + 1) * NVOX + idx] = __float2half(a.y);
        g_s1h[(size_t)(l * 3 + 2) * NVOX + idx] = __float2half(b);
    }
}

// ---------------------------------------------------------------------------
// Pass 2: blur along D, f32x2 packed. Tile 64d x 64w, 512 threads
// (16 warps x 4 d-outputs, warp-per-row). Register-pipelined staging:
// next label's s1 tile LDG'd into registers while current label computes.
// Dynamic smem: sb[3][94][64] f32 = 72 KB -> 3 blocks/SM.
// Combos: 0:(d0,h0) 1:(d1,h0) 2:(d2,h0) 3:(d0,h1) 4:(d1,h1) 5:(d0,h2)
// ---------------------------------------------------------------------------
#define P2_DR 64
#define P2_PP (P2_DR + 2*RAD)   // 94
#define P2_THREADS 512
#define NSTG  6                  // ceil(94*32 / 512)
#define SB_PLANE (P2_PP * 64)
#define P2_SMEM (3 * SB_PLANE * 4 + 128)

extern __shared__ float p2smem[];

__global__ __launch_bounds__(P2_THREADS) void pass2_kernel() {
    float* sb  = p2smem;                    // [3][94][64]
    float* sw0 = p2smem + 3 * SB_PLANE;
    int tid   = threadIdx.x;
    int wbase = blockIdx.x * 64;
    int h     = blockIdx.y;
    int dbase = blockIdx.z * P2_DR;
    if (tid < TAPS) sw0[tid] = g_w0[tid];
    int wi   = tid & 31;
    int grp  = tid >> 5;       // 0..15
    int dloc = grp * 4;

    unsigned int stg[3][NSTG];   // raw half2 bits of the staged tile

    auto load_label = [&](int l) {
#pragma unroll
        for (int c = 0; c < 3; ++c) {
            const __half* src = g_s1h + (size_t)(l * 3 + c) * NVOX + (size_t)h * WW + wbase;
#pragma unroll
            for (int j = 0; j < NSTG; ++j) {
                int idx = tid + j * P2_THREADS;
                unsigned int v = 0u;     // half2(0,0)
                if (idx < P2_PP * 32) {
                    int pp = idx >> 5, pr = idx & 31;
                    int dd = dbase + pp - RAD;
                    if (dd >= 0 && dd < DD)
                        v = *(const unsigned int*)(src + (size_t)dd * HW + 2 * pr);
                }
                stg[c][j] = v;
            }
        }
    };
    auto store_stage = [&]() {
#pragma unroll
        for (int c = 0; c < 3; ++c)
#pragma unroll
            for (int j = 0; j < NSTG; ++j) {
                int idx = tid + j * P2_THREADS;
                if (idx < P2_PP * 32) {
                    int pp = idx >> 5, pr = idx & 31;
                    float2 v = __half22float2(*(const __half2*)&stg[c][j]);
                    sb[c * SB_PLANE + pp * 64 + 2 * pr]     = v.x;
                    sb[c * SB_PLANE + pp * 64 + 2 * pr + 1] = v.y;
                }
            }
    };

    load_label(0);
    store_stage();
    __syncthreads();   // sb(l=0) + sw0 visible

#pragma unroll 1
    for (int l = 0; l < 8; ++l) {
        if (l < 7) load_label(l + 1);   // LDGs in flight during compute

        u64 acc[4][6];
#pragma unroll
        for (int o = 0; o < 4; ++o)
#pragma unroll
            for (int cc = 0; cc < 6; ++cc) acc[o][cc] = 0ull;

        u64 v0[4], v1[4], v2[4];
#pragma unroll
        for (int o = 0; o < 4; ++o) {
            v0[o] = *(const u64*)&sb[0 * SB_PLANE + (dloc + o) * 64 + 2 * wi];
            v1[o] = *(const u64*)&sb[1 * SB_PLANE + (dloc + o) * 64 + 2 * wi];
            v2[o] = *(const u64*)&sb[2 * SB_PLANE + (dloc + o) * 64 + 2 * wi];
        }
#pragma unroll
        for (int t = 0; t < TAPS; ++t) {
            float k0 = sw0[t];
            float dd = (float)(t - RAD);
            float k1 = k0 * dd;
            float k2 = k1 * dd;
            u64 K0 = pk2(k0, k0), K1 = pk2(k1, k1), K2 = pk2(k2, k2);
#pragma unroll
            for (int o = 0; o < 4; ++o) {
                acc[o][0] = ffma2(K0, v0[o], acc[o][0]);
                acc[o][1] = ffma2(K1, v0[o], acc[o][1]);
                acc[o][2] = ffma2(K2, v0[o], acc[o][2]);
                acc[o][3] = ffma2(K0, v1[o], acc[o][3]);
                acc[o][4] = ffma2(K1, v1[o], acc[o][4]);
                acc[o][5] = ffma2(K0, v2[o], acc[o][5]);
            }
            if (t < TAPS - 1) {
#pragma unroll
                for (int o = 0; o < 3; ++o) { v0[o] = v0[o+1]; v1[o] = v1[o+1]; v2[o] = v2[o+1]; }
                v0[3] = *(const u64*)&sb[0 * SB_PLANE + (dloc + t + 4) * 64 + 2 * wi];
                v1[3] = *(const u64*)&sb[1 * SB_PLANE + (dloc + t + 4) * 64 + 2 * wi];
                v2[3] = *(const u64*)&sb[2 * SB_PLANE + (dloc + t + 4) * 64 + 2 * wi];
            }
        }
        __syncthreads();               // all reads of sb(l) done
        if (l < 7) store_stage();      // sb <- l+1

        size_t obase = (size_t)(dbase + dloc) * HW + (size_t)h * WW + wbase + 2 * wi;
#pragma unroll
        for (int o = 0; o < 4; ++o)
#pragma unroll
            for (int cc = 0; cc < 6; ++cc) {
                float lo, hi; upk2(lo, hi, acc[o][cc]);
                __half2 hv = __floats2half2_rn(lo, hi);
                __stcs((__half2*)&g_s2h[(size_t)(l * 6 + cc) * NVOX + obase + (size_t)o * HW], hv);
            }
        if (l < 7) __syncthreads();    // sb(l+1) ready
    }
}

// ---------------------------------------------------------------------------
// Pass 3: blur along W + descriptor assembly, own-label only.
// smem voxel-major fp16, 8 halves per label (16B aligned): one LDS.128 per tap.
// Row pad 72 halves = 9 bank-quads -> conflict-free LDS.128 phases.
// ---------------------------------------------------------------------------
__global__ __launch_bounds__(128, 10) void pass3_kernel(const int* __restrict__ seg,
                                                        float* __restrict__ out) {
    __shared__ __align__(16) __half sm[WW][72];   // 18432 B
    __shared__ float sw0[TAPS];
    int w = threadIdx.x;
    int h = blockIdx.x;
    int d = blockIdx.y;
    if (w < TAPS) sw0[w] = g_w0[w];
    size_t base = (size_t)d * HW + (size_t)h * WW;
    for (int ch = 0; ch < 48; ++ch) {
        int l = ch / 6, c = ch - 6 * l;
        unsigned short v = __ldcs((const unsigned short*)&g_s2h[(size_t)ch * NVOX + base + w]);
        *(unsigned short*)&sm[w][l * 8 + c] = v;
    }
    __syncthreads();

    int L = seg[base + w];
    float r0=0,r1=0,r2=0,r3=0,r4=0,r5=0,r6=0,r7=0,r8=0,r9=0;
    if (L != 0) {
        int lb8 = (L - 1) * 8;
        // packed accumulators: A=(m0,m1d) B=(mdd,m1h) C=(mdh,mhh)
        //                      Dp=(m1w,mdw) E=(junk,mhw) F=(mww,junk)
        u64 A=0ull, B=0ull, C=0ull, Dp=0ull, E=0ull, F=0ull;
        int t0 = (w < RAD) ? RAD - w : 0;
        int t1 = (w > WW - 1 - RAD) ? (WW - 1 - w) + RAD : TAPS - 1;
        for (int t = t0; t <= t1; ++t) {
            int pos = w + t - RAD;
            float k0 = sw0[t];
            float dd = (float)(t - RAD);
            float k1 = k0 * dd;
            float k2 = k1 * dd;
            uint4 pck = *(const uint4*)&sm[pos][lb8];     // 8 halves, 6 used
            float2 a01 = __half22float2(*(const __half2*)&pck.x);
            float2 a23 = __half22float2(*(const __half2*)&pck.y);
            float2 a45 = __half22float2(*(const __half2*)&pck.z);
            u64 P01 = pk2(a01.x, a01.y);
            u64 P23 = pk2(a23.x, a23.y);
            u64 P45 = pk2(a45.x, a45.y);
            u64 K0 = pk2(k0, k0), K1 = pk2(k1, k1), K2 = pk2(k2, k2);
            A  = ffma2(K0, P01, A);
            B  = ffma2(K0, P23, B);
            C  = ffma2(K0, P45, C);
            Dp = ffma2(K1, P01, Dp);
            E  = ffma2(K1, P23, E);   // .y accumulates k1*V3 = mhw
            F  = ffma2(K2, P01, F);   // .x accumulates k2*V0 = mww
        }
        float m0, m1d, mdd, m1h, mdh, mhh, m1w, mdw, junk, mhw, mww;
        upk2(m0, m1d, A); upk2(mdd, m1h, B); upk2(mdh, mhh, C);
        upk2(m1w, mdw, Dp); upk2(junk, mhw, E); upk2(mww, junk, F);

        float inv = 1.0f / m0;   // m0 >= w(0)^3 > 0 at a labeled voxel
        float od = m1d * inv, oh = m1h * inv, ow = m1w * inv;
        const float is2 = 1.0f / 25.0f;   // 1/sigma^2
        r0 = fmaf(od, 0.1f, 0.5f);        // (off/sigma)*0.5 + 0.5, sigma=5
        r1 = fmaf(oh, 0.1f, 0.5f);
        r2 = fmaf(ow, 0.1f, 0.5f);
        r3 = (mdd * inv - od * od) * is2;
        r4 = (mhh * inv - oh * oh) * is2;
        r5 = (mww * inv - ow * ow) * is2;
        r6 = (mdh * inv - od * oh) * is2;
        r7 = (mhw * inv - oh * ow) * is2;
        r8 = (mdw * inv - od * ow) * is2;
        r9 = m0;
    }
    float rr[10] = {r0,r1,r2,r3,r4,r5,r6,r7,r8,r9};
#pragma unroll
    for (int c = 0; c < 10; ++c) {
        float v = rr[c];
        v = fminf(fmaxf(v, 0.0f), 1.0f);
        __stcs(&out[(size_t)c * NVOX + base + w], v);
    }
}

// ---------------------------------------------------------------------------
extern "C" void kernel_launch(void* const* d_in, const int* in_sizes, int n_in,
                              void* d_out, int out_size) {
    const int* seg = (const int*)d_in[0];
    // d_in[1] (coords) is a deterministic meshgrid == voxel indices; the
    // local-moment formulation makes it unnecessary.
    float* out = (float*)d_out;

    static int configured = 0;
    if (!configured) {
        cudaFuncSetAttribute(pass2_kernel,
                             cudaFuncAttributeMaxDynamicSharedMemorySize, P2_SMEM);
        configured = 1;
    }

    init_weights_kernel<<<1, 32>>>();
    pass1_kernel<<<dim3(HH, DD), 128>>>(seg);
    pass2_kernel<<<dim3(WW / 64, HH, DD / P2_DR), P2_THREADS, P2_SMEM>>>();
    pass3_kernel<<<dim3(HH, DD), 128>>>(seg, out);
}

// round 10
// speedup vs baseline: 1.1384x; 1.1384x over previous
#include <cuda_runtime.h>
#include <cuda_fp16.h>
#include <math.h>

#define DD 128
#define HH 128
#define WW 128
#define HW (HH*WW)
#define NVOX (DD*HH*WW)
#define RAD 15
#define TAPS 31

// fp16 intermediates: pass1 out (8 labels x 3 h-orders), pass2 out (8 x 6 combos)
__device__ __half g_s1h[(size_t)24 * NVOX];   // ~100 MB
__device__ __half g_s2h[(size_t)48 * NVOX];   // ~201 MB
__device__ float  g_w0[TAPS];

// ---------------- f32x2 packed helpers ----------------
typedef unsigned long long u64;

__device__ __forceinline__ u64 pk2(float lo, float hi) {
    u64 r; asm("mov.b64 %0, {%1, %2};" : "=l"(r) : "f"(lo), "f"(hi)); return r;
}
__device__ __forceinline__ void upk2(float& lo, float& hi, u64 v) {
    asm("mov.b64 {%0, %1}, %2;" : "=f"(lo), "=f"(hi) : "l"(v));
}
__device__ __forceinline__ u64 ffma2(u64 a, u64 b, u64 c) {
    u64 r; asm("fma.rn.f32x2 %0, %1, %2, %3;" : "=l"(r) : "l"(a), "l"(b), "l"(c)); return r;
}

// ---------------------------------------------------------------------------
// Weight init: float expf + warp reduction.
// ---------------------------------------------------------------------------
__global__ void init_weights_kernel() {
    int t = threadIdx.x;   // 32 threads
    float d = (float)(t - RAD);
    float v = (t < TAPS) ? expf(-0.5f * d * d / 25.0f) : 0.0f;
    float s = v;
#pragma unroll
    for (int o = 16; o; o >>= 1) s += __shfl_xor_sync(0xffffffffu, s, o);
    if (t < TAPS) g_w0[t] = v / s;
}

// ---------------------------------------------------------------------------
// Pass 1: blur along H. One-hot: per tap add (k0,k1) to the matched label's
// float2 slot + k2 to a scalar slot. Slot 8 is a dummy sink for label 0.
// ---------------------------------------------------------------------------
__global__ __launch_bounds__(128) void pass1_kernel(const int* __restrict__ seg) {
    __shared__ float2 accA[9 * 128];   // (k0,k1) per label slot
    __shared__ float  accB[9 * 128];   // k2 per label slot
    __shared__ float  sw0[TAPS];
    int w = threadIdx.x;
    int h = blockIdx.x;
    int d = blockIdx.y;
    if (w < TAPS) sw0[w] = g_w0[w];
#pragma unroll
    for (int i = 0; i < 9; ++i) {
        accA[i * 128 + w] = make_float2(0.0f, 0.0f);
        accB[i * 128 + w] = 0.0f;
    }
    __syncthreads();   // for sw0 only

    int lo = h - RAD; if (lo < 0) lo = 0;
    int hi = h + RAD; if (hi > HH - 1) hi = HH - 1;
    const int* p = seg + (size_t)d * HW + w;
    for (int hh = lo; hh <= hi; ++hh) {
        int s = __ldg(p + (size_t)hh * WW);
        int t = hh - h + RAD;
        float k0 = sw0[t];
        float dd = (float)(hh - h);
        float k1 = k0 * dd;
        float k2 = k1 * dd;
        int slot = (s == 0) ? 8 : (s - 1);
        int off  = slot * 128 + w;
        float2 a = accA[off];
        a.x += k0; a.y += k1;
        accA[off] = a;
        accB[off] += k2;
    }
    size_t idx = (size_t)d * HW + (size_t)h * WW + w;
#pragma unroll
    for (int l = 0; l < 8; ++l) {
        float2 a = accA[l * 128 + w];
        float  b = accB[l * 128 + w];
        g_s1h[(size_t)(l * 3 + 0) * NVOX + idx] = __float2half(a.x);
        g_s1h[(size_t)(l * 3 + 1) * NVOX + idx] = __float2half(a.y);
        g_s1h[(size_t)(l * 3 + 2) * NVOX + idx] = __float2half(b);
    }
}

// ---------------------------------------------------------------------------
// Pass 2: blur along D, f32x2 packed. Tile 32d x 64w, 256 threads,
// warp-per-row. Software-pipelined staging: next label's s1 tile is LDG'd
// into registers (as raw half2 bits) while the current label computes.
// Combos: 0:(d0,h0) 1:(d1,h0) 2:(d2,h0) 3:(d0,h1) 4:(d1,h1) 5:(d0,h2)
// ---------------------------------------------------------------------------
#define P2_DR 32
#define P2_PP (P2_DR + 2*RAD)   // 62
#define NSTG  8                  // ceil(62*32 / 256)

__global__ __launch_bounds__(256) void pass2_kernel() {
    __shared__ __align__(16) float sb[3][P2_PP][64];   // 47616 B
    __shared__ float sw0[TAPS];
    int tid   = threadIdx.x;
    int wbase = blockIdx.x * 64;
    int h     = blockIdx.y;
    int dbase = blockIdx.z * P2_DR;
    if (tid < TAPS) sw0[tid] = g_w0[tid];
    int wi   = tid & 31;
    int grp  = tid >> 5;
    int dloc = grp * 4;

    unsigned int stg[3][NSTG];   // raw half2 bits of the staged tile

    // ---- register-stage label l: issue LDGs (no smem touched) ----
    auto load_label = [&](int l) {
#pragma unroll
        for (int c = 0; c < 3; ++c) {
            const __half* src = g_s1h + (size_t)(l * 3 + c) * NVOX + (size_t)h * WW + wbase;
#pragma unroll
            for (int j = 0; j < NSTG; ++j) {
                int idx = tid + j * 256;
                unsigned int v = 0u;     // half2(0,0)
                if (idx < P2_PP * 32) {
                    int pp = idx >> 5, pr = idx & 31;
                    int dd = dbase + pp - RAD;
                    if (dd >= 0 && dd < DD)
                        v = *(const unsigned int*)(src + (size_t)dd * HW + 2 * pr);
                }
                stg[c][j] = v;
            }
        }
    };
    // ---- convert + store staged registers into sb ----
    auto store_stage = [&]() {
#pragma unroll
        for (int c = 0; c < 3; ++c)
#pragma unroll
            for (int j = 0; j < NSTG; ++j) {
                int idx = tid + j * 256;
                if (idx < P2_PP * 32) {
                    int pp = idx >> 5, pr = idx & 31;
                    float2 v = __half22float2(*(const __half2*)&stg[c][j]);
                    sb[c][pp][2 * pr]     = v.x;
                    sb[c][pp][2 * pr + 1] = v.y;
                }
            }
    };

    load_label(0);
    store_stage();
    __syncthreads();   // sb(l=0) + sw0 visible

#pragma unroll 1
    for (int l = 0; l < 8; ++l) {
        if (l < 7) load_label(l + 1);   // LDGs in flight during compute

        u64 acc[4][6];
#pragma unroll
        for (int o = 0; o < 4; ++o)
#pragma unroll
            for (int cc = 0; cc < 6; ++cc) acc[o][cc] = 0ull;

        u64 v0[4], v1[4], v2[4];
#pragma unroll
        for (int o = 0; o < 4; ++o) {
            v0[o] = *(const u64*)&sb[0][dloc + o][2 * wi];
            v1[o] = *(const u64*)&sb[1][dloc + o][2 * wi];
            v2[o] = *(const u64*)&sb[2][dloc + o][2 * wi];
        }
#pragma unroll
        for (int t = 0; t < TAPS; ++t) {
            float k0 = sw0[t];
            float dd = (float)(t - RAD);
            float k1 = k0 * dd;
            float k2 = k1 * dd;
            u64 K0 = pk2(k0, k0), K1 = pk2(k1, k1), K2 = pk2(k2, k2);
#pragma unroll
            for (int o = 0; o < 4; ++o) {
                acc[o][0] = ffma2(K0, v0[o], acc[o][0]);
                acc[o][1] = ffma2(K1, v0[o], acc[o][1]);
                acc[o][2] = ffma2(K2, v0[o], acc[o][2]);
                acc[o][3] = ffma2(K0, v1[o], acc[o][3]);
                acc[o][4] = ffma2(K1, v1[o], acc[o][4]);
                acc[o][5] = ffma2(K0, v2[o], acc[o][5]);
            }
            if (t < TAPS - 1) {
#pragma unroll
                for (int o = 0; o < 3; ++o) { v0[o] = v0[o+1]; v1[o] = v1[o+1]; v2[o] = v2[o+1]; }
                v0[3] = *(const u64*)&sb[0][dloc + t + 4][2 * wi];
                v1[3] = *(const u64*)&sb[1][dloc + t + 4][2 * wi];
                v2[3] = *(const u64*)&sb[2][dloc + t + 4][2 * wi];
            }
        }
        __syncthreads();               // all reads of sb(l) done
        if (l < 7) store_stage();      // sb <- l+1

        size_t obase = (size_t)(dbase + dloc) * HW + (size_t)h * WW + wbase + 2 * wi;
#pragma unroll
        for (int o = 0; o < 4; ++o)
#pragma unroll
            for (int cc = 0; cc < 6; ++cc) {
                float lo, hi; upk2(lo, hi, acc[o][cc]);
                __half2 hv = __floats2half2_rn(lo, hi);
                __stcs((__half2*)&g_s2h[(size_t)(l * 6 + cc) * NVOX + obase + (size_t)o * HW], hv);
            }
        if (l < 7) __syncthreads();    // sb(l+1) ready
    }
}

// ---------------------------------------------------------------------------
// Pass 3: blur along W + descriptor assembly, own-label only.
// Staging: 48 LDG.16 into registers (48-deep MLP), pack per label into uint4,
// then 8x STS.128 per thread (2-way conflict) instead of 48x STS.16 (4-way):
// ~6x fewer staging wavefronts. Tap loop: one LDS.128 per tap, row pitch
// 72 halves = 9 bank-quads -> conflict-free.
// ---------------------------------------------------------------------------
__global__ __launch_bounds__(128, 10) void pass3_kernel(const int* __restrict__ seg,
                                                        float* __restrict__ out) {
    __shared__ __align__(16) __half sm[WW][72];   // 18432 B
    __shared__ float sw0[TAPS];
    int w = threadIdx.x;
    int h = blockIdx.x;
    int d = blockIdx.y;
    if (w < TAPS) sw0[w] = g_w0[w];
    size_t base = (size_t)d * HW + (size_t)h * WW;

    unsigned int vals[48];
#pragma unroll
    for (int ch = 0; ch < 48; ++ch)
        vals[ch] = __ldcs((const unsigned short*)&g_s2h[(size_t)ch * NVOX + base + w]);
#pragma unroll
    for (int l = 0; l < 8; ++l) {
        uint4 pk;
        pk.x = vals[l * 6 + 0] | (vals[l * 6 + 1] << 16);
        pk.y = vals[l * 6 + 2] | (vals[l * 6 + 3] << 16);
        pk.z = vals[l * 6 + 4] | (vals[l * 6 + 5] << 16);
        pk.w = 0u;
        *(uint4*)&sm[w][l * 8] = pk;
    }
    __syncthreads();

    int L = seg[base + w];
    float r0=0,r1=0,r2=0,r3=0,r4=0,r5=0,r6=0,r7=0,r8=0,r9=0;
    if (L != 0) {
        int lb8 = (L - 1) * 8;
        // packed accumulators: A=(m0,m1d) B=(mdd,m1h) C=(mdh,mhh)
        //                      Dp=(m1w,mdw) E=(junk,mhw) F=(mww,junk)
        u64 A=0ull, B=0ull, C=0ull, Dp=0ull, E=0ull, F=0ull;
        int t0 = (w < RAD) ? RAD - w : 0;
        int t1 = (w > WW - 1 - RAD) ? (WW - 1 - w) + RAD : TAPS - 1;
        for (int t = t0; t <= t1; ++t) {
            int pos = w + t - RAD;
            float k0 = sw0[t];
            float dd = (float)(t - RAD);
            float k1 = k0 * dd;
            float k2 = k1 * dd;
            uint4 pck = *(const uint4*)&sm[pos][lb8];     // 8 halves, 6 used
            float2 a01 = __half22float2(*(const __half2*)&pck.x);
            float2 a23 = __half22float2(*(const __half2*)&pck.y);
            float2 a45 = __half22float2(*(const __half2*)&pck.z);
            u64 P01 = pk2(a01.x, a01.y);
            u64 P23 = pk2(a23.x, a23.y);
            u64 P45 = pk2(a45.x, a45.y);
            u64 K0 = pk2(k0, k0), K1 = pk2(k1, k1), K2 = pk2(k2, k2);
            A  = ffma2(K0, P01, A);
            B  = ffma2(K0, P23, B);
            C  = ffma2(K0, P45, C);
            Dp = ffma2(K1, P01, Dp);
            E  = ffma2(K1, P23, E);   // .y accumulates k1*V3 = mhw
            F  = ffma2(K2, P01, F);   // .x accumulates k2*V0 = mww
        }
        float m0, m1d, mdd, m1h, mdh, mhh, m1w, mdw, junk, mhw, mww;
        upk2(m0, m1d, A); upk2(mdd, m1h, B); upk2(mdh, mhh, C);
        upk2(m1w, mdw, Dp); upk2(junk, mhw, E); upk2(mww, junk, F);

        float inv = 1.0f / m0;   // m0 >= w(0)^3 > 0 at a labeled voxel
        float od = m1d * inv, oh = m1h * inv, ow = m1w * inv;
        const float is2 = 1.0f / 25.0f;   // 1/sigma^2
        r0 = fmaf(od, 0.1f, 0.5f);        // (off/sigma)*0.5 + 0.5, sigma=5
        r1 = fmaf(oh, 0.1f, 0.5f);
        r2 = fmaf(ow, 0.1f, 0.5f);
        r3 = (mdd * inv - od * od) * is2;
        r4 = (mhh * inv - oh * oh) * is2;
        r5 = (mww * inv - ow * ow) * is2;
        r6 = (mdh * inv - od * oh) * is2;
        r7 = (mhw * inv - oh * ow) * is2;
        r8 = (mdw * inv - od * ow) * is2;
        r9 = m0;
    }
    float rr[10] = {r0,r1,r2,r3,r4,r5,r6,r7,r8,r9};
#pragma unroll
    for (int c = 0; c < 10; ++c) {
        float v = rr[c];
        v = fminf(fmaxf(v, 0.0f), 1.0f);
        __stcs(&out[(size_t)c * NVOX + base + w], v);
    }
}

// ---------------------------------------------------------------------------
extern "C" void kernel_launch(void* const* d_in, const int* in_sizes, int n_in,
                              void* d_out, int out_size) {
    const int* seg = (const int*)d_in[0];
    // d_in[1] (coords) is a deterministic meshgrid == voxel indices; the
    // local-moment formulation makes it unnecessary.
    float* out = (float*)d_out;

    init_weights_kernel<<<1, 32>>>();
    pass1_kernel<<<dim3(HH, DD), 128>>>(seg);
    pass2_kernel<<<dim3(WW / 64, HH, DD / P2_DR), 256>>>();
    pass3_kernel<<<dim3(HH, DD), 128>>>(seg, out);
}